// round 8
// baseline (speedup 1.0000x reference)
#include <cuda_runtime.h>

// Problem constants (hard-coded in reference)
#define S7      7
#define CELLS   49
#define NCELLS  802816            // 16384 * 49
#define IMGF    448.0f
#define CELLF   64.0f

#define GRID    784               // blocks
#define TPB     256               // threads per block
#define SWEEP   (GRID * TPB)      // 200704 cells per sweep
#define ITERS   (NCELLS / SWEEP)  // 4 (exact)

// Scratch (allocation-free: __device__ globals)
__device__ float    g_partials[GRID];
__device__ unsigned g_count = 0;

__device__ __forceinline__ void decode_box(float p0, float p1, float p2, float p3,
                                           float gx, float gy,
                                           float& x1, float& y1, float& x2, float& y2) {
    float cx = fmaf(p0, CELLF, gx);
    float cy = fmaf(p1, CELLF, gy);
    float w  = p2 * IMGF;
    float h  = p3 * IMGF;
    x1 = fminf(fmaxf(cx - 0.5f * w, 0.0f), IMGF);
    y1 = fminf(fmaxf(cy - 0.5f * h, 0.0f), IMGF);
    x2 = fminf(fmaxf(cx + 0.5f * w, 0.0f), IMGF);
    y2 = fminf(fmaxf(cy + 0.5f * h, 0.0f), IMGF);
}

__device__ __forceinline__ float iou_fn(float ax1, float ay1, float ax2, float ay2,
                                        float bx1, float by1, float bx2, float by2) {
    float l  = fmaxf(ax1, bx1);
    float r  = fminf(ax2, bx2);
    float t  = fmaxf(ay1, by1);
    float bo = fminf(ay2, by2);
    bool  m  = (l < r) && (t < bo);
    float inter = (r - l) * (bo - t);
    float uni   = (ax2 - ax1) * (ay2 - ay1) + (bx2 - bx1) * (by2 - by1);
    float denom = uni - inter;
    return m ? (inter / denom) : 0.0f;
}

__global__ __launch_bounds__(TPB)
void yolo_loss_fused(const float* __restrict__ inp,   // [B,30,7,7]
                     const float* __restrict__ tgt,   // [B,7,7,30]
                     float* __restrict__ out)
{
    // Target tile: 256 cells x 30 floats, staged via coalesced float4 loads
    __shared__ float  s_t[TPB * 30];                   // 30720 B
    __shared__ float  s_wsum[TPB / 32];
    __shared__ double s_dsum[TPB / 32];
    __shared__ bool   s_last;

    const int tid = threadIdx.x;
    float acc = 0.0f;

#pragma unroll
    for (int it = 0; it < ITERS; ++it) {
        const int base = it * SWEEP + blockIdx.x * TPB;   // multiple of 256

        // ---- stage target tile: 1920 float4, fully coalesced ----
        const float4* src = (const float4*)(tgt + (size_t)base * 30);
        float4* dst = (float4*)s_t;
        for (int i = tid; i < (TPB * 30) / 4; i += TPB)
            dst[i] = src[i];
        __syncthreads();

        // ---- per-cell loss ----
        const int n    = base + tid;
        const int b    = n / CELLS;
        const int cell = n - b * CELLS;
        const int row  = cell / S7;
        const int col  = cell - row * S7;
        const float gx = (float)col * CELLF;
        const float gy = (float)row * CELLF;

        const float* xin = inp + b * 1470 + cell;   // coalesced per k across warp
        const float* tp  = s_t + tid * 30;          // smem row (conflict deg <= 2)

        float x[10], t[10];
#pragma unroll
        for (int k = 0; k < 10; k++) x[k] = __ldg(xin + k * CELLS);
#pragma unroll
        for (int k = 0; k < 10; k++) t[k] = tp[k];

        float px1a, py1a, px2a, py2a, px1b, py1b, px2b, py2b;
        float tx1a, ty1a, tx2a, ty2a, tx1b, ty1b, tx2b, ty2b;
        decode_box(x[0], x[1], x[2], x[3], gx, gy, px1a, py1a, px2a, py2a);
        decode_box(x[5], x[6], x[7], x[8], gx, gy, px1b, py1b, px2b, py2b);
        decode_box(t[0], t[1], t[2], t[3], gx, gy, tx1a, ty1a, tx2a, ty2a);
        decode_box(t[5], t[6], t[7], t[8], gx, gy, tx1b, ty1b, tx2b, ty2b);

        float iou1 = iou_fn(px1a, py1a, px2a, py2a, tx1a, ty1a, tx2a, ty2a);
        float iou2 = iou_fn(px1b, py1b, px2b, py2b, tx1b, ty1b, tx2b, ty2b);

        bool  msk = iou1 < iou2;
        float iou = msk ? iou2 : iou1;
        float s0 = msk ? x[5] : x[0];
        float s1 = msk ? x[6] : x[1];
        float s2 = msk ? x[7] : x[2];
        float s3 = msk ? x[8] : x[3];
        float s4 = msk ? x[9] : x[4];

        bool hasObj = (t[4] == 1.0f);

        if (hasObj) {
            float d0 = s0 - t[0], d1 = s1 - t[1];
            float coord = d0 * d0 + d1 * d1;
            float ds2 = sqrtf(s2) - sqrtf(t[2]);
            float ds3 = sqrtf(s3) - sqrtf(t[3]);
            float size = ds2 * ds2 + ds3 * ds3;
            float dc = s4 - iou;
            float conf = dc * dc;
            float cls = 0.0f;
#pragma unroll
            for (int k = 10; k < 30; k++) {
                float d = __ldg(xin + k * CELLS) - tp[k];
                cls = fmaf(d, d, cls);
            }
            acc += 5.0f * coord + 5.0f * size + conf + cls;
        } else {
            acc += 0.5f * (s4 * s4);
        }
        __syncthreads();   // protect s_t before next stage
    }

    // ---- block reduction (fp32, <= 1024 cells of O(1..10) magnitude) ----
    const unsigned fullmask = 0xFFFFFFFFu;
#pragma unroll
    for (int off = 16; off > 0; off >>= 1)
        acc += __shfl_down_sync(fullmask, acc, off);

    const int lane = tid & 31;
    const int wid  = tid >> 5;
    if (lane == 0) s_wsum[wid] = acc;
    __syncthreads();
    if (wid == 0) {
        float v = (lane < TPB / 32) ? s_wsum[lane] : 0.0f;
#pragma unroll
        for (int off = 4; off > 0; off >>= 1)
            v += __shfl_down_sync(fullmask, v, off);
        if (lane == 0) {
            g_partials[blockIdx.x] = v;
            __threadfence();
            unsigned prev = atomicAdd(&g_count, 1u);
            s_last = (prev == GRID - 1);
        }
    }
    __syncthreads();

    // ---- deterministic last-block final reduction (double, fixed order) ----
    if (s_last) {
        __threadfence();
        double s = 0.0;
        for (int i = tid; i < GRID; i += TPB) {
            float p;
            asm volatile("ld.global.cg.f32 %0, [%1];" : "=f"(p) : "l"(g_partials + i));
            s += (double)p;
        }
#pragma unroll
        for (int off = 16; off > 0; off >>= 1)
            s += __shfl_down_sync(fullmask, s, off);
        if (lane == 0) s_dsum[wid] = s;
        __syncthreads();
        if (wid == 0) {
            double v = (lane < TPB / 32) ? s_dsum[lane] : 0.0;
#pragma unroll
            for (int off = 4; off > 0; off >>= 1)
                v += __shfl_down_sync(fullmask, v, off);
            if (lane == 0) {
                out[0] = (float)v;
                g_count = 0;           // reset for next graph replay
            }
        }
    }
}

extern "C" void kernel_launch(void* const* d_in, const int* in_sizes, int n_in,
                              void* d_out, int out_size)
{
    const float* inp = (const float*)d_in[0];   // input_ [B,30,7,7] f32
    const float* tgt = (const float*)d_in[1];   // target [B,7,7,30] f32
    float* out = (float*)d_out;

    yolo_loss_fused<<<GRID, TPB>>>(inp, tgt, out);
}

// round 9
// speedup vs baseline: 1.1110x; 1.1110x over previous
#include <cuda_runtime.h>

// Problem constants (hard-coded in reference)
#define S7      7
#define CELLS   49
#define NCELLS  802816            // 16384 * 49
#define IMGF    448.0f
#define CELLF   64.0f

#define TPB     256
#define GRID    (NCELLS / TPB)    // 3136 exactly

// Scratch (allocation-free: __device__ globals)
__device__ float    g_partials[GRID];
__device__ unsigned g_count = 0;

__device__ __forceinline__ void decode_box(float p0, float p1, float p2, float p3,
                                           float gx, float gy,
                                           float& x1, float& y1, float& x2, float& y2) {
    float cx = fmaf(p0, CELLF, gx);
    float cy = fmaf(p1, CELLF, gy);
    float w  = p2 * IMGF;
    float h  = p3 * IMGF;
    x1 = fminf(fmaxf(cx - 0.5f * w, 0.0f), IMGF);
    y1 = fminf(fmaxf(cy - 0.5f * h, 0.0f), IMGF);
    x2 = fminf(fmaxf(cx + 0.5f * w, 0.0f), IMGF);
    y2 = fminf(fmaxf(cy + 0.5f * h, 0.0f), IMGF);
}

__device__ __forceinline__ float iou_fn(float ax1, float ay1, float ax2, float ay2,
                                        float bx1, float by1, float bx2, float by2) {
    float l  = fmaxf(ax1, bx1);
    float r  = fminf(ax2, bx2);
    float t  = fmaxf(ay1, by1);
    float bo = fminf(ay2, by2);
    bool  m  = (l < r) && (t < bo);
    float inter = (r - l) * (bo - t);
    float uni   = (ax2 - ax1) * (ay2 - ay1) + (bx2 - bx1) * (by2 - by1);
    float denom = uni - inter;
    return m ? (inter / denom) : 0.0f;
}

__global__ __launch_bounds__(TPB)
void yolo_loss_onepass(const float* __restrict__ inp,   // [B,30,7,7]
                       const float* __restrict__ tgt,   // [B,7,7,30]
                       float* __restrict__ out)
{
    __shared__ float  s_wsum[TPB / 32];
    __shared__ double s_dsum[TPB / 32];
    __shared__ bool   s_last;

    const int tid = threadIdx.x;
    const int n   = blockIdx.x * TPB + tid;           // < NCELLS always

    const int b    = n / CELLS;
    const int cell = n - b * CELLS;
    const int row  = cell / S7;
    const int col  = cell - row * S7;
    const float gx = (float)col * CELLF;
    const float gy = (float)row * CELLF;

    // input: (b, k, cell) at b*1470 + k*49 + cell -> coalesced across warp per k
    const float* xin = inp + b * 1470 + cell;
    // target row: n*30 floats -> 8B-aligned (120B stride), contiguous per thread
    const float2* tp2 = (const float2*)(tgt + (size_t)n * 30);

    float x[10], t[10];
#pragma unroll
    for (int k = 0; k < 10; k++) x[k] = __ldg(xin + k * CELLS);
#pragma unroll
    for (int k = 0; k < 5; k++) {
        float2 v = __ldg(tp2 + k);
        t[2 * k]     = v.x;
        t[2 * k + 1] = v.y;
    }

    float px1a, py1a, px2a, py2a, px1b, py1b, px2b, py2b;
    float tx1a, ty1a, tx2a, ty2a, tx1b, ty1b, tx2b, ty2b;
    decode_box(x[0], x[1], x[2], x[3], gx, gy, px1a, py1a, px2a, py2a);
    decode_box(x[5], x[6], x[7], x[8], gx, gy, px1b, py1b, px2b, py2b);
    decode_box(t[0], t[1], t[2], t[3], gx, gy, tx1a, ty1a, tx2a, ty2a);
    decode_box(t[5], t[6], t[7], t[8], gx, gy, tx1b, ty1b, tx2b, ty2b);

    float iou1 = iou_fn(px1a, py1a, px2a, py2a, tx1a, ty1a, tx2a, ty2a);
    float iou2 = iou_fn(px1b, py1b, px2b, py2b, tx1b, ty1b, tx2b, ty2b);

    bool  msk = iou1 < iou2;                 // second box responsible
    float iou = msk ? iou2 : iou1;
    float s0 = msk ? x[5] : x[0];
    float s1 = msk ? x[6] : x[1];
    float s2 = msk ? x[7] : x[2];
    float s3 = msk ? x[8] : x[3];
    float s4 = msk ? x[9] : x[4];

    bool hasObj = (t[4] == 1.0f);

    float loss;
    if (hasObj) {
        float d0 = s0 - t[0], d1 = s1 - t[1];
        float coord = d0 * d0 + d1 * d1;
        float ds2 = sqrtf(s2) - sqrtf(t[2]);
        float ds3 = sqrtf(s3) - sqrtf(t[3]);
        float size = ds2 * ds2 + ds3 * ds3;
        float dc = s4 - iou;
        float conf = dc * dc;
        float cls = 0.0f;
#pragma unroll
        for (int k = 0; k < 10; k++) {       // class: t[10..29] via float2
            float2 tv = __ldg(tp2 + 5 + k);
            float da = __ldg(xin + (10 + 2 * k) * CELLS) - tv.x;
            float db = __ldg(xin + (11 + 2 * k) * CELLS) - tv.y;
            cls = fmaf(da, da, cls);
            cls = fmaf(db, db, cls);
        }
        loss = 5.0f * coord + 5.0f * size + conf + cls;
    } else {
        loss = 0.5f * (s4 * s4);             // noobj term only
    }

    // ---- block reduction (fp32, 256 O(1..10) terms) ----
    const unsigned fullmask = 0xFFFFFFFFu;
#pragma unroll
    for (int off = 16; off > 0; off >>= 1)
        loss += __shfl_down_sync(fullmask, loss, off);

    const int lane = tid & 31;
    const int wid  = tid >> 5;
    if (lane == 0) s_wsum[wid] = loss;
    __syncthreads();
    if (wid == 0) {
        float v = (lane < TPB / 32) ? s_wsum[lane] : 0.0f;
#pragma unroll
        for (int off = 4; off > 0; off >>= 1)
            v += __shfl_down_sync(fullmask, v, off);
        if (lane == 0) {
            g_partials[blockIdx.x] = v;
            __threadfence();
            unsigned prev = atomicAdd(&g_count, 1u);
            s_last = (prev == GRID - 1);
        }
    }
    __syncthreads();

    // ---- deterministic last-block final reduction (double, fixed order) ----
    if (s_last) {
        __threadfence();
        double s = 0.0;
        for (int i = tid; i < GRID; i += TPB) {
            float p;
            asm volatile("ld.global.cg.f32 %0, [%1];" : "=f"(p) : "l"(g_partials + i));
            s += (double)p;
        }
#pragma unroll
        for (int off = 16; off > 0; off >>= 1)
            s += __shfl_down_sync(fullmask, s, off);
        if (lane == 0) s_dsum[wid] = s;
        __syncthreads();
        if (wid == 0) {
            double v = (lane < TPB / 32) ? s_dsum[lane] : 0.0;
#pragma unroll
            for (int off = 4; off > 0; off >>= 1)
                v += __shfl_down_sync(fullmask, v, off);
            if (lane == 0) {
                out[0] = (float)v;
                g_count = 0;           // reset for next graph replay
            }
        }
    }
}

extern "C" void kernel_launch(void* const* d_in, const int* in_sizes, int n_in,
                              void* d_out, int out_size)
{
    const float* inp = (const float*)d_in[0];   // input_ [B,30,7,7] f32
    const float* tgt = (const float*)d_in[1];   // target [B,7,7,30] f32
    float* out = (float*)d_out;

    yolo_loss_onepass<<<GRID, TPB>>>(inp, tgt, out);
}